// round 4
// baseline (speedup 1.0000x reference)
#include <cuda_runtime.h>
#include <cuda_bf16.h>
#include <math.h>

#define VOCAB   50257
#define DIM     768
#define RANK    16
#define SCALING 2.0f

#define NB1     148         // k1 blocks
#define ROWS1   340         // rows per k1 block
#define HROWS   170         // rows per half
#define NBP     (NB1 * 2)   // partial sets (per row-half)

#define K3_BLOCKS 128
#define K3_TOK    128       // tokens per k3 block (2 lanes x 64)

typedef unsigned long long u64;

// ---------------- scratch (no allocations allowed) ----------------
__device__ __align__(16) float g_partM[NBP * DIM * RANK];   // [p][d*16+r]
__device__ __align__(16) float g_partE2[NBP * DIM];
__device__ __align__(16) float g_partG[NB1 * 256];
__device__ __align__(16) float g_M[DIM * RANK];
__device__ __align__(16) float g_E2[DIM];
__device__ __align__(16) float g_G[256];
__device__ __align__(16) float g_sc[DIM];
__device__ __align__(16) float g_Bs[RANK * DIM];

// ---------------- f32x2 helpers ----------------
__device__ __forceinline__ u64 pack2(float lo, float hi) {
    u64 r;
    asm("mov.b64 %0, {%1, %2};" : "=l"(r) : "f"(lo), "f"(hi));
    return r;
}
__device__ __forceinline__ void unpack2(u64 v, float& lo, float& hi) {
    asm("mov.b64 {%0, %1}, %2;" : "=f"(lo), "=f"(hi) : "l"(v));
}
__device__ __forceinline__ u64 fma2(u64 a, u64 b, u64 c) {
    u64 d;
    asm("fma.rn.f32x2 %0, %1, %2, %3;" : "=l"(d) : "l"(a), "l"(b), "l"(c));
    return d;
}
__device__ __forceinline__ u64 mul2(u64 a, u64 b) {
    u64 d;
    asm("mul.rn.f32x2 %0, %1, %2;" : "=l"(d) : "l"(a), "l"(b));
    return d;
}

// =================================================================
// Kernel 1: stream E once (float4 per thread = 4 columns), compute
// per-(block,row-half) partials of E2[d], M[d,r]; per-block Gram.
// 384 threads = 192 col-threads x 2 row-halves.
// A pre-duplicated in shared as (a,a) u64 -> 1 LDS.64 per r per row.
// =================================================================
__global__ __launch_bounds__(384, 1)
void k1_stats(const float* __restrict__ E, const float* __restrict__ A) {
    __shared__ __align__(16) u64 shAd[RANK][ROWS1 + 4];   // ~44KB
    const int b    = blockIdx.x;
    const int tid  = threadIdx.x;
    const int v0   = b * ROWS1;
    const int rows = min(ROWS1, VOCAB - v0);

    // stage A chunk, duplicated lanes
    for (int idx = tid; idx < rows * RANK; idx += 384) {
        int i = idx >> 4, r = idx & 15;
        float a = A[(size_t)(v0 + i) * RANK + r];
        shAd[r][i] = pack2(a, a);
    }
    __syncthreads();

    const int h  = tid >= 192;          // row-half
    const int cg = tid - (h ? 192 : 0); // column group (4 cols)
    const int r0 = h * HROWS;
    const int rh = min(HROWS, rows - r0);   // >= 107 always

    const float4* cp = reinterpret_cast<const float4*>(E + (size_t)(v0 + r0) * DIM) + cg;

    u64 accM[RANK][2];
    u64 accE[2] = {0ull, 0ull};
#pragma unroll
    for (int r = 0; r < RANK; r++) { accM[r][0] = 0ull; accM[r][1] = 0ull; }

    const int full4 = rh & ~3;

    float4 cur[4];
#pragma unroll
    for (int k = 0; k < 4; k++) cur[k] = cp[(size_t)min(k, rh - 1) * (DIM / 4)];

    for (int base = 0; base < full4; base += 4) {
        float4 nxt[4];
#pragma unroll
        for (int k = 0; k < 4; k++) {
            int idx = min(base + 4 + k, rh - 1);
            nxt[k] = cp[(size_t)idx * (DIM / 4)];
        }
#pragma unroll
        for (int q = 0; q < 4; q++) {
            const int i = r0 + base + q;
            u64 e0 = pack2(cur[q].x, cur[q].y);
            u64 e1 = pack2(cur[q].z, cur[q].w);
            accE[0] = fma2(e0, e0, accE[0]);
            accE[1] = fma2(e1, e1, accE[1]);
#pragma unroll
            for (int r = 0; r < RANK; r++) {
                u64 a = shAd[r][i];
                accM[r][0] = fma2(a, e0, accM[r][0]);
                accM[r][1] = fma2(a, e1, accM[r][1]);
            }
        }
#pragma unroll
        for (int k = 0; k < 4; k++) cur[k] = nxt[k];
    }
    // tail rows
    for (int i2 = full4; i2 < rh; i2++) {
        float4 ev = cp[(size_t)i2 * (DIM / 4)];
        const int i = r0 + i2;
        u64 e0 = pack2(ev.x, ev.y);
        u64 e1 = pack2(ev.z, ev.w);
        accE[0] = fma2(e0, e0, accE[0]);
        accE[1] = fma2(e1, e1, accE[1]);
#pragma unroll
        for (int r = 0; r < RANK; r++) {
            u64 a = shAd[r][i];
            accM[r][0] = fma2(a, e0, accM[r][0]);
            accM[r][1] = fma2(a, e1, accM[r][1]);
        }
    }

    // write partials (vectorized)
    const int p = b * 2 + h;
    {
        float e2v[4];
        unpack2(accE[0], e2v[0], e2v[1]);
        unpack2(accE[1], e2v[2], e2v[3]);
        *reinterpret_cast<float4*>(g_partE2 + (size_t)p * DIM + 4 * cg) =
            make_float4(e2v[0], e2v[1], e2v[2], e2v[3]);
    }
    {
        float4* dstM = reinterpret_cast<float4*>(g_partM + (size_t)p * (DIM * RANK) + 64 * cg);
#pragma unroll
        for (int j = 0; j < 4; j++) {
#pragma unroll
            for (int q = 0; q < 4; q++) {
                float v[4];
#pragma unroll
                for (int k = 0; k < 4; k++) {
                    float lo, hi;
                    unpack2(accM[4 * q + k][j >> 1], lo, hi);
                    v[k] = (j & 1) ? hi : lo;
                }
                dstM[j * 4 + q] = make_float4(v[0], v[1], v[2], v[3]);
            }
        }
    }

    // Gram partials (cheap tail; threads 0..255, one (r,r') pair each)
    if (tid < 256) {
        int r = tid >> 4, r2 = tid & 15;
        float g = 0.f;
        for (int i = 0; i < rows; i++) {
            float a1 = reinterpret_cast<const float*>(&shAd[r][i])[0];
            float a2 = reinterpret_cast<const float*>(&shAd[r2][i])[0];
            g += a1 * a2;
        }
        g_partG[b * 256 + tid] = g;
    }
}

// =================================================================
// Kernel 2: deterministic reduction of partials.
// grid 52 x 256 = 13312 = 12288 (M) + 768 (E2) + 256 (G)
// =================================================================
__global__ void k2_reduce() {
    int j = blockIdx.x * 256 + threadIdx.x;
    if (j < DIM * RANK) {
        float s = 0.f;
#pragma unroll 4
        for (int p = 0; p < NBP; p++) s += g_partM[(size_t)p * (DIM * RANK) + j];
        g_M[j] = s;
    } else if (j < DIM * RANK + DIM) {
        int d = j - DIM * RANK;
        float s = 0.f;
#pragma unroll 4
        for (int p = 0; p < NBP; p++) s += g_partE2[p * DIM + d];
        g_E2[d] = s;
    } else {
        int t = j - (DIM * RANK + DIM);
        float s = 0.f;
#pragma unroll 4
        for (int b = 0; b < NB1; b++) s += g_partG[b * 256 + t];
        g_G[t] = s;
    }
}

// =================================================================
// Kernel 2b: sc[d] = mag[d]/norm[d];  Bs[r,d] = s*B[r,d]*sc[d]
// =================================================================
__global__ void k2b_norms(const float* __restrict__ B, const float* __restrict__ mag) {
    int d = blockIdx.x * 256 + threadIdx.x;
    float bb[RANK];
#pragma unroll
    for (int r = 0; r < RANK; r++) bb[r] = B[r * DIM + d];
    float cross = 0.f, quad = 0.f;
#pragma unroll
    for (int r = 0; r < RANK; r++) {
        float t = 0.f;
#pragma unroll
        for (int r2 = 0; r2 < RANK; r2++) t += g_G[r * RANK + r2] * bb[r2];
        quad  += bb[r] * t;
        cross += g_M[d * RANK + r] * bb[r];
    }
    float n2 = g_E2[d] + 2.f * SCALING * cross + SCALING * SCALING * quad;
    float n  = fmaxf(sqrtf(n2), 1e-8f);
    float sc = mag[d] / n;
    g_sc[d] = sc;
#pragma unroll
    for (int r = 0; r < RANK; r++) g_Bs[r * DIM + d] = SCALING * bb[r] * sc;
}

// =================================================================
// Kernel 3: gather.  out[t,:] = E[v,:]*sc + sum_r A[v,r]*Bs[r,:]
// 768 threads = 384 col-threads (2 cols, u64) x 2 token-lanes.
// Bs in registers (f32x2 non-dup), token-A dup-packed in shared.
// =================================================================
__global__ __launch_bounds__(768, 1)
void k3_gather(const int* __restrict__ ids, const float* __restrict__ E,
               const float* __restrict__ A, float* __restrict__ out) {
    __shared__ int shT[K3_TOK];
    __shared__ __align__(16) u64 shAd[RANK][K3_TOK];   // 16KB
    const int b    = blockIdx.x;
    const int tid  = threadIdx.x;
    const int t0   = b * K3_TOK;
    const int lane = tid >= 384;
    const int cg   = tid - (lane ? 384 : 0);   // cols 2cg, 2cg+1

    // Bs / sc in registers as f32x2 over the column pair
    u64 rb[RANK], scd;
#pragma unroll
    for (int r = 0; r < RANK; r++)
        rb[r] = *reinterpret_cast<const u64*>(g_Bs + r * DIM + 2 * cg);
    scd = *reinterpret_cast<const u64*>(g_sc + 2 * cg);

    if (tid < K3_TOK) shT[tid] = ids[t0 + tid];
    __syncthreads();
    for (int idx = tid; idx < K3_TOK * RANK; idx += 768) {
        int i = idx >> 4, r = idx & 15;
        float a = A[(size_t)shT[i] * RANK + r];
        shAd[r][i] = pack2(a, a);
    }
    __syncthreads();

    const int i0 = lane * (K3_TOK / 2);   // 64 tokens per lane

    u64 cur[4];
#pragma unroll
    for (int k = 0; k < 4; k++)
        cur[k] = *reinterpret_cast<const u64*>(E + (size_t)shT[i0 + k] * DIM + 2 * cg);

    for (int base = 0; base < K3_TOK / 2; base += 4) {
        u64 nxt[4];
        const int nb = (base + 4 < K3_TOK / 2) ? base + 4 : base;
#pragma unroll
        for (int k = 0; k < 4; k++)
            nxt[k] = *reinterpret_cast<const u64*>(E + (size_t)shT[i0 + nb + k] * DIM + 2 * cg);
#pragma unroll
        for (int q = 0; q < 4; q++) {
            const int i = i0 + base + q;
            u64 acc = mul2(cur[q], scd);
#pragma unroll
            for (int r = 0; r < RANK; r++)
                acc = fma2(shAd[r][i], rb[r], acc);
            *reinterpret_cast<u64*>(out + (size_t)(t0 + i) * DIM + 2 * cg) = acc;
        }
#pragma unroll
        for (int k = 0; k < 4; k++) cur[k] = nxt[k];
    }
}

// =================================================================
extern "C" void kernel_launch(void* const* d_in, const int* in_sizes, int n_in,
                              void* d_out, int out_size) {
    const int*   ids = (const int*)d_in[0];    // [8,2048] int32
    const float* E   = (const float*)d_in[1];  // [50257,768]
    const float* A   = (const float*)d_in[2];  // [50257,16]
    const float* B   = (const float*)d_in[3];  // [16,768]
    const float* mag = (const float*)d_in[4];  // [768]
    float* out = (float*)d_out;                // [8,2048,768] fp32

    k1_stats <<<NB1, 384>>>(E, A);
    k2_reduce<<<52, 256>>>();
    k2b_norms<<<3, 256>>>(B, mag);
    k3_gather<<<K3_BLOCKS, 768>>>(ids, E, A, out);
}

// round 5
// speedup vs baseline: 1.0018x; 1.0018x over previous
#include <cuda_runtime.h>
#include <cuda_bf16.h>
#include <math.h>

#define VOCAB   50257
#define DIM     768
#define RANK    16
#define SCALING 2.0f
#define NTOK    16384

#define NB1     296         // k1 blocks (2 per SM)
#define ROWS1   170         // rows per k1 block (296*170 >= 50257)
#define NBP     296         // partial sets

#define K3B     296         // k3 blocks (2 per SM)
#define K3T     56          // tokens per k3 block (296*56 >= 16384)

typedef unsigned long long u64;

// ---------------- scratch (no allocations allowed) ----------------
__device__ __align__(16) float g_partM[NBP * DIM * RANK];   // [p][d*16+r]
__device__ __align__(16) float g_partE2[NBP * DIM];
__device__ __align__(16) float g_partG[NBP * 256];
__device__ __align__(16) float g_M[DIM * RANK];
__device__ __align__(16) float g_E2[DIM];
__device__ __align__(16) float g_G[256];
__device__ __align__(16) float g_sc[DIM];
__device__ __align__(16) float g_Bs[RANK * DIM];

// ---------------- f32x2 helpers ----------------
__device__ __forceinline__ u64 pack2(float lo, float hi) {
    u64 r;
    asm("mov.b64 %0, {%1, %2};" : "=l"(r) : "f"(lo), "f"(hi));
    return r;
}
__device__ __forceinline__ void unpack2(u64 v, float& lo, float& hi) {
    asm("mov.b64 {%0, %1}, %2;" : "=f"(lo), "=f"(hi) : "l"(v));
}
__device__ __forceinline__ u64 fma2(u64 a, u64 b, u64 c) {
    u64 d;
    asm("fma.rn.f32x2 %0, %1, %2, %3;" : "=l"(d) : "l"(a), "l"(b), "l"(c));
    return d;
}
__device__ __forceinline__ u64 mul2(u64 a, u64 b) {
    u64 d;
    asm("mul.rn.f32x2 %0, %1, %2;" : "=l"(d) : "l"(a), "l"(b));
    return d;
}

// =================================================================
// Kernel 1: stream E once. 384 threads = 384 column-pairs (u64).
// f32x2 lanes = (col 2t, col 2t+1). A duplicated (a,a) in shared.
// 6-deep register prefetch; 2 blocks/SM -> 24 warps/SM, 36KB/SM
// outstanding load bytes.
// =================================================================
#define PF1 6
__global__ __launch_bounds__(384, 2)
void k1_stats(const float* __restrict__ E, const float* __restrict__ A) {
    __shared__ __align__(16) u64 shAd[RANK][ROWS1 + 2];   // ~22KB
    const int b    = blockIdx.x;
    const int tid  = threadIdx.x;
    const int v0   = b * ROWS1;
    const int rows = min(ROWS1, VOCAB - v0);   // >= 107

    // stage A chunk, duplicated lanes (coalesced: addr = v0*16 + idx)
    for (int idx = tid; idx < rows * RANK; idx += 384) {
        int i = idx >> 4, r = idx & 15;
        float a = A[(size_t)v0 * RANK + idx];
        shAd[r][i] = pack2(a, a);
    }
    __syncthreads();

    const u64* cp = reinterpret_cast<const u64*>(E + (size_t)v0 * DIM) + tid;

    u64 accM[RANK];
    u64 accE = 0ull;
#pragma unroll
    for (int r = 0; r < RANK; r++) accM[r] = 0ull;

    const int fullc = rows - rows % PF1;

    u64 cur[PF1];
#pragma unroll
    for (int k = 0; k < PF1; k++) cur[k] = cp[(size_t)min(k, rows - 1) * (DIM / 2)];

    for (int base = 0; base < fullc; base += PF1) {
        u64 nxt[PF1];
#pragma unroll
        for (int k = 0; k < PF1; k++) {
            int idx = min(base + PF1 + k, rows - 1);
            nxt[k] = cp[(size_t)idx * (DIM / 2)];
        }
#pragma unroll
        for (int q = 0; q < PF1; q++) {
            const int i = base + q;
            u64 e = cur[q];
            accE = fma2(e, e, accE);
#pragma unroll
            for (int r = 0; r < RANK; r++)
                accM[r] = fma2(shAd[r][i], e, accM[r]);
        }
#pragma unroll
        for (int k = 0; k < PF1; k++) cur[k] = nxt[k];
    }
    // tail rows (< PF1): cur[q] already holds row fullc+q (unclamped there)
    for (int i = fullc; i < rows; i++) {
        u64 e = cur[i - fullc];
        accE = fma2(e, e, accE);
#pragma unroll
        for (int r = 0; r < RANK; r++)
            accM[r] = fma2(shAd[r][i], e, accM[r]);
    }

    // write partials: E2 as u64 (lanes = col pair), M as 8x float4
    *reinterpret_cast<u64*>(g_partE2 + (size_t)b * DIM + 2 * tid) = accE;
    {
        float4* dstM = reinterpret_cast<float4*>(g_partM + (size_t)b * (DIM * RANK) + (size_t)2 * tid * RANK);
        float lo[RANK], hi[RANK];
#pragma unroll
        for (int r = 0; r < RANK; r++) unpack2(accM[r], lo[r], hi[r]);
#pragma unroll
        for (int q = 0; q < 4; q++)
            dstM[q] = make_float4(lo[4 * q], lo[4 * q + 1], lo[4 * q + 2], lo[4 * q + 3]);
#pragma unroll
        for (int q = 0; q < 4; q++)
            dstM[4 + q] = make_float4(hi[4 * q], hi[4 * q + 1], hi[4 * q + 2], hi[4 * q + 3]);
    }

    // Gram partials (threads 0..255, one (r,r') pair each)
    if (tid < 256) {
        int r = tid >> 4, r2 = tid & 15;
        float g = 0.f;
        for (int i = 0; i < rows; i++) {
            float a1 = reinterpret_cast<const float*>(&shAd[r][i])[0];
            float a2 = reinterpret_cast<const float*>(&shAd[r2][i])[0];
            g += a1 * a2;
        }
        g_partG[b * 256 + tid] = g;
    }
}

// =================================================================
// Kernel 2: deterministic reduction of the 296 partial sets.
// grid 52 x 256 = 13312 = 12288 (M) + 768 (E2) + 256 (G)
// =================================================================
__global__ void k2_reduce() {
    int j = blockIdx.x * 256 + threadIdx.x;
    if (j < DIM * RANK) {
        float s = 0.f;
#pragma unroll 4
        for (int p = 0; p < NBP; p++) s += g_partM[(size_t)p * (DIM * RANK) + j];
        g_M[j] = s;
    } else if (j < DIM * RANK + DIM) {
        int d = j - DIM * RANK;
        float s = 0.f;
#pragma unroll 4
        for (int p = 0; p < NBP; p++) s += g_partE2[p * DIM + d];
        g_E2[d] = s;
    } else {
        int t = j - (DIM * RANK + DIM);
        float s = 0.f;
#pragma unroll 4
        for (int p = 0; p < NBP; p++) s += g_partG[p * 256 + t];
        g_G[t] = s;
    }
}

// =================================================================
// Kernel 2b: sc[d] = mag[d]/norm[d];  Bs[r,d] = s*B[r,d]*sc[d]
// =================================================================
__global__ void k2b_norms(const float* __restrict__ B, const float* __restrict__ mag) {
    int d = blockIdx.x * 256 + threadIdx.x;
    float bb[RANK];
#pragma unroll
    for (int r = 0; r < RANK; r++) bb[r] = B[r * DIM + d];
    float cross = 0.f, quad = 0.f;
#pragma unroll
    for (int r = 0; r < RANK; r++) {
        float t = 0.f;
#pragma unroll
        for (int r2 = 0; r2 < RANK; r2++) t += g_G[r * RANK + r2] * bb[r2];
        quad  += bb[r] * t;
        cross += g_M[d * RANK + r] * bb[r];
    }
    float n2 = g_E2[d] + 2.f * SCALING * cross + SCALING * SCALING * quad;
    float n  = fmaxf(sqrtf(n2), 1e-8f);
    float sc = mag[d] / n;
    g_sc[d] = sc;
#pragma unroll
    for (int r = 0; r < RANK; r++) g_Bs[r * DIM + d] = SCALING * bb[r] * sc;
}

// =================================================================
// Kernel 3: gather. 384 threads = 384 column-pairs, 56 tokens/block,
// grid 296 (2 blocks/SM, 24 warps/SM). Bs in registers (f32x2),
// token-A dup-packed in shared, 4-deep token prefetch.
// =================================================================
#define PF3 4
__global__ __launch_bounds__(384, 2)
void k3_gather(const int* __restrict__ ids, const float* __restrict__ E,
               const float* __restrict__ A, float* __restrict__ out) {
    __shared__ int shT[K3T];
    __shared__ __align__(16) u64 shAd[RANK][K3T];   // 7KB
    const int b    = blockIdx.x;
    const int tid  = threadIdx.x;
    const int t0   = b * K3T;
    const int ntok = min(K3T, NTOK - t0);           // 56, 32, or <=0

    // Bs / sc in registers as f32x2 over the column pair
    u64 rb[RANK], scd;
#pragma unroll
    for (int r = 0; r < RANK; r++)
        rb[r] = *reinterpret_cast<const u64*>(g_Bs + r * DIM + 2 * tid);
    scd = *reinterpret_cast<const u64*>(g_sc + 2 * tid);

    if (tid < K3T) shT[tid] = ids[min(t0 + tid, NTOK - 1)];
    __syncthreads();
    for (int idx = tid; idx < K3T * RANK; idx += 384) {
        int i = idx >> 4, r = idx & 15;
        float a = A[(size_t)shT[i] * RANK + r];
        shAd[r][i] = pack2(a, a);
    }
    __syncthreads();

    if (ntok <= 0) return;

    const u64* Ep = reinterpret_cast<const u64*>(E) + tid;
    const int fullc = ntok - ntok % PF3;

    u64 cur[PF3];
#pragma unroll
    for (int k = 0; k < PF3; k++)
        cur[k] = Ep[(size_t)shT[min(k, ntok - 1)] * (DIM / 2)];

    for (int base = 0; base < fullc; base += PF3) {
        u64 nxt[PF3];
#pragma unroll
        for (int k = 0; k < PF3; k++) {
            int idx = min(base + PF3 + k, ntok - 1);
            nxt[k] = Ep[(size_t)shT[idx] * (DIM / 2)];
        }
#pragma unroll
        for (int q = 0; q < PF3; q++) {
            const int i = base + q;
            u64 acc = mul2(cur[q], scd);
#pragma unroll
            for (int r = 0; r < RANK; r++)
                acc = fma2(shAd[r][i], rb[r], acc);
            *reinterpret_cast<u64*>(out + (size_t)(t0 + i) * DIM + 2 * tid) = acc;
        }
#pragma unroll
        for (int k = 0; k < PF3; k++) cur[k] = nxt[k];
    }
    for (int i = fullc; i < ntok; i++) {
        u64 acc = mul2(cur[i - fullc], scd);
#pragma unroll
        for (int r = 0; r < RANK; r++)
            acc = fma2(shAd[r][i], rb[r], acc);
        *reinterpret_cast<u64*>(out + (size_t)(t0 + i) * DIM + 2 * tid) = acc;
    }
}

// =================================================================
extern "C" void kernel_launch(void* const* d_in, const int* in_sizes, int n_in,
                              void* d_out, int out_size) {
    const int*   ids = (const int*)d_in[0];    // [8,2048] int32
    const float* E   = (const float*)d_in[1];  // [50257,768]
    const float* A   = (const float*)d_in[2];  // [50257,16]
    const float* B   = (const float*)d_in[3];  // [16,768]
    const float* mag = (const float*)d_in[4];  // [768]
    float* out = (float*)d_out;                // [8,2048,768] fp32

    k1_stats <<<NB1, 384>>>(E, A);
    k2_reduce<<<52, 256>>>();
    k2b_norms<<<3, 256>>>(B, mag);
    k3_gather<<<K3B, 384>>>(ids, E, A, out);
}

// round 6
// speedup vs baseline: 1.2834x; 1.2811x over previous
#include <cuda_runtime.h>
#include <cuda_bf16.h>
#include <math.h>

#define VOCAB   50257
#define DIM     768
#define RANK    16
#define SCALING 2.0f
#define NTOK    16384

#define NB1     148         // k1 blocks (1 per SM)
#define ROWS1   340         // rows per k1 block (148*340 >= 50257)
#define NBP     148

#define K3B     148
#define K3T     111         // tokens per k3 block (148*111 >= 16384)

typedef unsigned long long u64;

// ---------------- scratch (no allocations allowed) ----------------
__device__ __align__(16) float g_partM[NBP * DIM * RANK];   // [p][d*16+r]
__device__ __align__(16) float g_partE2[NBP * DIM];
__device__ __align__(16) float g_partG[NBP * 256];
__device__ __align__(16) float g_M[DIM * RANK];
__device__ __align__(16) float g_E2[DIM];
__device__ __align__(16) float g_G[256];
__device__ __align__(16) float g_sc[DIM];
__device__ __align__(16) float g_Bs[RANK * DIM];

// ---------------- f32x2 helpers ----------------
__device__ __forceinline__ u64 pack2(float lo, float hi) {
    u64 r;
    asm("mov.b64 %0, {%1, %2};" : "=l"(r) : "f"(lo), "f"(hi));
    return r;
}
__device__ __forceinline__ void unpack2(u64 v, float& lo, float& hi) {
    asm("mov.b64 {%0, %1}, %2;" : "=f"(lo), "=f"(hi) : "l"(v));
}
__device__ __forceinline__ u64 fma2(u64 a, u64 b, u64 c) {
    u64 d;
    asm("fma.rn.f32x2 %0, %1, %2, %3;" : "=l"(d) : "l"(a), "l"(b), "l"(c));
    return d;
}

// =================================================================
// Kernel 1: stream E once. 768 threads = 768 columns (1 each).
// f32x2 lanes = RANK-pairs: accM[q] = (M[c,2q], M[c,2q+1]).
// A row-major in shared -> 4 LDS.128 per row (broadcast), E scalar
// LDG.32 coalesced, 8-row prefetch.
// =================================================================
#define PF1 8
__global__ __launch_bounds__(768, 1)
void k1_stats(const float* __restrict__ E, const float* __restrict__ A) {
    __shared__ __align__(16) float shA[ROWS1 * RANK];   // 21.25KB
    const int b    = blockIdx.x;
    const int tid  = threadIdx.x;
    const int v0   = b * ROWS1;
    const int rows = min(ROWS1, VOCAB - v0);   // >= 277

    // stage A chunk row-major (fully coalesced)
    for (int idx = tid; idx < rows * RANK; idx += 768)
        shA[idx] = A[(size_t)v0 * RANK + idx];
    __syncthreads();

    const float* cp = E + (size_t)v0 * DIM + tid;

    u64 accM[8];
#pragma unroll
    for (int q = 0; q < 8; q++) accM[q] = 0ull;
    float accE = 0.f;

    const int fullc = rows - rows % PF1;

    float cur[PF1];
#pragma unroll
    for (int k = 0; k < PF1; k++) cur[k] = cp[(size_t)min(k, rows - 1) * DIM];

    for (int base = 0; base < fullc; base += PF1) {
        float nxt[PF1];
#pragma unroll
        for (int k = 0; k < PF1; k++) {
            int idx = min(base + PF1 + k, rows - 1);
            nxt[k] = cp[(size_t)idx * DIM];
        }
#pragma unroll
        for (int q = 0; q < PF1; q++) {
            const int i = base + q;
            const float e = cur[q];
            const u64 ed = pack2(e, e);
            const ulonglong2* ap = reinterpret_cast<const ulonglong2*>(shA + i * RANK);
#pragma unroll
            for (int q2 = 0; q2 < 4; q2++) {
                ulonglong2 av = ap[q2];                 // LDS.128 (broadcast)
                accM[2 * q2]     = fma2(av.x, ed, accM[2 * q2]);
                accM[2 * q2 + 1] = fma2(av.y, ed, accM[2 * q2 + 1]);
            }
            accE = fmaf(e, e, accE);
        }
#pragma unroll
        for (int k = 0; k < PF1; k++) cur[k] = nxt[k];
    }
    // tail rows (cur[q] holds row fullc+q unclamped for q < rows-fullc)
    for (int i = fullc; i < rows; i++) {
        const float e = cur[i - fullc];
        const u64 ed = pack2(e, e);
        const ulonglong2* ap = reinterpret_cast<const ulonglong2*>(shA + i * RANK);
#pragma unroll
        for (int q2 = 0; q2 < 4; q2++) {
            ulonglong2 av = ap[q2];
            accM[2 * q2]     = fma2(av.x, ed, accM[2 * q2]);
            accM[2 * q2 + 1] = fma2(av.y, ed, accM[2 * q2 + 1]);
        }
        accE = fmaf(e, e, accE);
    }

    // write partials: M[c,0..15] contiguous (4 STG.128), E2 scalar
    {
        float4* dstM = reinterpret_cast<float4*>(g_partM + (size_t)b * (DIM * RANK) + tid * RANK);
#pragma unroll
        for (int q2 = 0; q2 < 4; q2++) {
            float l0, h0, l1, h1;
            unpack2(accM[2 * q2], l0, h0);
            unpack2(accM[2 * q2 + 1], l1, h1);
            dstM[q2] = make_float4(l0, h0, l1, h1);
        }
    }
    g_partE2[b * DIM + tid] = accE;

    // Gram partials (threads 0..255, one (r,r') pair each)
    if (tid < 256) {
        int r = tid >> 4, r2 = tid & 15;
        float g = 0.f;
        for (int i = 0; i < rows; i++)
            g += shA[i * RANK + r] * shA[i * RANK + r2];
        g_partG[b * 256 + tid] = g;
    }
}

// =================================================================
// Kernel 2: deterministic reduction of the 148 partial sets.
// grid 52 x 256 = 13312 = 12288 (M) + 768 (E2) + 256 (G)
// =================================================================
__global__ void k2_reduce() {
    int j = blockIdx.x * 256 + threadIdx.x;
    if (j < DIM * RANK) {
        float s = 0.f;
#pragma unroll 4
        for (int p = 0; p < NBP; p++) s += g_partM[(size_t)p * (DIM * RANK) + j];
        g_M[j] = s;
    } else if (j < DIM * RANK + DIM) {
        int d = j - DIM * RANK;
        float s = 0.f;
#pragma unroll 4
        for (int p = 0; p < NBP; p++) s += g_partE2[p * DIM + d];
        g_E2[d] = s;
    } else {
        int t = j - (DIM * RANK + DIM);
        float s = 0.f;
#pragma unroll 4
        for (int p = 0; p < NBP; p++) s += g_partG[p * 256 + t];
        g_G[t] = s;
    }
}

// =================================================================
// Kernel 2b: sc[d] = mag[d]/norm[d];  Bs[r,d] = s*B[r,d]*sc[d]
// =================================================================
__global__ void k2b_norms(const float* __restrict__ B, const float* __restrict__ mag) {
    int d = blockIdx.x * 256 + threadIdx.x;
    float bb[RANK];
#pragma unroll
    for (int r = 0; r < RANK; r++) bb[r] = B[r * DIM + d];
    float cross = 0.f, quad = 0.f;
#pragma unroll
    for (int r = 0; r < RANK; r++) {
        float t = 0.f;
#pragma unroll
        for (int r2 = 0; r2 < RANK; r2++) t += g_G[r * RANK + r2] * bb[r2];
        quad  += bb[r] * t;
        cross += g_M[d * RANK + r] * bb[r];
    }
    float n2 = g_E2[d] + 2.f * SCALING * cross + SCALING * SCALING * quad;
    float n  = fmaxf(sqrtf(n2), 1e-8f);
    float sc = mag[d] / n;
    g_sc[d] = sc;
#pragma unroll
    for (int r = 0; r < RANK; r++) g_Bs[r * DIM + d] = SCALING * bb[r] * sc;
}

// =================================================================
// Kernel 3: gather. 768 threads = 768 columns, 111 tokens/block.
// Bs as rank-pair f32x2 registers; A rows row-major in shared
// (4 LDS.128/token); horizontal fold; scalar E/out.
// =================================================================
#define PF3 4
__global__ __launch_bounds__(768, 1)
void k3_gather(const int* __restrict__ ids, const float* __restrict__ E,
               const float* __restrict__ A, float* __restrict__ out) {
    __shared__ int shT[K3T];
    __shared__ __align__(16) float shA[K3T * RANK];   // ~7KB
    const int b    = blockIdx.x;
    const int tid  = threadIdx.x;
    const int t0   = b * K3T;
    const int ntok = min(K3T, NTOK - t0);             // 67..111

    // Bs rank-pairs + sc for this column
    u64 rb[8];
#pragma unroll
    for (int q = 0; q < 8; q++)
        rb[q] = pack2(g_Bs[(2 * q) * DIM + tid], g_Bs[(2 * q + 1) * DIM + tid]);
    const float sc = g_sc[tid];

    if (tid < ntok) shT[tid] = ids[t0 + tid];
    __syncthreads();
    for (int idx = tid; idx < ntok * RANK; idx += 768)
        shA[idx] = A[(size_t)shT[idx >> 4] * RANK + (idx & 15)];
    __syncthreads();

    const float* Ep = E + tid;
    const int fullc = ntok - ntok % PF3;

    float cur[PF3];
#pragma unroll
    for (int k = 0; k < PF3; k++)
        cur[k] = Ep[(size_t)shT[min(k, ntok - 1)] * DIM];

    for (int base = 0; base < fullc; base += PF3) {
        float nxt[PF3];
#pragma unroll
        for (int k = 0; k < PF3; k++) {
            int idx = min(base + PF3 + k, ntok - 1);
            nxt[k] = Ep[(size_t)shT[idx] * DIM];
        }
#pragma unroll
        for (int q = 0; q < PF3; q++) {
            const int i = base + q;
            const ulonglong2* ap = reinterpret_cast<const ulonglong2*>(shA + i * RANK);
            u64 acc = 0ull;
#pragma unroll
            for (int q2 = 0; q2 < 4; q2++) {
                ulonglong2 av = ap[q2];                 // LDS.128 (broadcast)
                acc = fma2(av.x, rb[2 * q2], acc);
                acc = fma2(av.y, rb[2 * q2 + 1], acc);
            }
            float lo, hi;
            unpack2(acc, lo, hi);
            out[(size_t)(t0 + i) * DIM + tid] = fmaf(cur[q], sc, lo + hi);
        }
#pragma unroll
        for (int k = 0; k < PF3; k++) cur[k] = nxt[k];
    }
    for (int i = fullc; i < ntok; i++) {
        const ulonglong2* ap = reinterpret_cast<const ulonglong2*>(shA + i * RANK);
        u64 acc = 0ull;
#pragma unroll
        for (int q2 = 0; q2 < 4; q2++) {
            ulonglong2 av = ap[q2];
            acc = fma2(av.x, rb[2 * q2], acc);
            acc = fma2(av.y, rb[2 * q2 + 1], acc);
        }
        float lo, hi;
        unpack2(acc, lo, hi);
        out[(size_t)(t0 + i) * DIM + tid] = fmaf(cur[i - fullc], sc, lo + hi);
    }
}

// =================================================================
extern "C" void kernel_launch(void* const* d_in, const int* in_sizes, int n_in,
                              void* d_out, int out_size) {
    const int*   ids = (const int*)d_in[0];    // [8,2048] int32
    const float* E   = (const float*)d_in[1];  // [50257,768]
    const float* A   = (const float*)d_in[2];  // [50257,16]
    const float* B   = (const float*)d_in[3];  // [16,768]
    const float* mag = (const float*)d_in[4];  // [768]
    float* out = (float*)d_out;                // [8,2048,768] fp32

    k1_stats <<<NB1, 768>>>(E, A);
    k2_reduce<<<52, 256>>>();
    k2b_norms<<<3, 256>>>(B, mag);
    k3_gather<<<K3B, 768>>>(ids, E, A, out);
}